// round 3
// baseline (speedup 1.0000x reference)
#include <cuda_runtime.h>

// Problem constants (fixed for this instance)
#define HW_   262144          // H*W = 512*512
#define D_    32
#define B_    8
#define C_    19
#define N_    2097152         // B*H*W
#define EPS_  1e-8f

// ---------------- scratch (device globals; no allocation allowed) ----------
__device__ float g_sum[C_ * D_];     // per-class feature sums
__device__ float g_cnt[C_];          // per-class counts
__device__ float g_segcos[C_];       // per-class sum of cos
__device__ float g_center[C_ * D_];  // centers
__device__ float g_cnorm[C_];        // center norms
__device__ int   g_is64;             // targets dtype flag

// ---------------- K0: zero scratch + detect target dtype -------------------
__global__ void k_zero(const void* __restrict__ tgt) {
    int i = threadIdx.x;
    if (i < C_ * D_) { g_sum[i] = 0.f; g_center[i] = 0.f; }
    if (i < C_) { g_cnt[i] = 0.f; g_segcos[i] = 0.f; g_cnorm[i] = 0.f; }
    if (i == 639) {
        // int64 labels in [0,19): every odd 32-bit word is 0.
        const unsigned* w = (const unsigned*)tgt;
        int is64 = 1;
        #pragma unroll
        for (int k = 0; k < 16; k++)
            if (w[2 * k + 1] != 0u) is64 = 0;
        g_is64 = is64;
    }
}

// ---------------- K1: segment sums + counts (lane = dim) --------------------
// grid 1024 x block 256 (8 warps). Each warp: 256 contiguous pixels.
// Warp-private smem accumulators, non-atomic RMW (each (c,lane) cell owned by
// exactly one lane of one warp).
#define K1_BLOCKS 1024
#define K1_WARPS  8

__global__ void __launch_bounds__(256) k_sums(const float* __restrict__ in,
                                              const void* __restrict__ tgt) {
    __shared__ float acc[K1_WARPS][C_ * D_];
    __shared__ float cnt[K1_WARPS][C_];

    const int w    = threadIdx.x >> 5;
    const int lane = threadIdx.x & 31;
    const int is64 = g_is64;

    for (int i = lane; i < C_ * D_; i += 32) acc[w][i] = 0.f;
    if (lane < C_) cnt[w][lane] = 0.f;
    __syncwarp();

    const int gw  = blockIdx.x * K1_WARPS + w;
    const int p0  = gw * 256;                 // pixels [p0, p0+256)
    const int b   = p0 >> 18;                 // / HW_
    const int hw0 = p0 & (HW_ - 1);
    const float* base = in + (size_t)b * ((size_t)D_ * HW_) +
                        (size_t)lane * HW_ + hw0;
    float* ac = &acc[w][lane];

    const long long* t64 = (const long long*)tgt;
    const int*       t32 = (const int*)tgt;

    #pragma unroll 1
    for (int g = 0; g < 8; ++g) {
        const int pg = p0 + g * 32;
        int lab = is64 ? (int)t64[pg + lane] : t32[pg + lane];

        // full 128B line per lane: 32 pixels of dim `lane`
        const float4* p4 = (const float4*)(base + g * 32);
        float v[32];
        #pragma unroll
        for (int k = 0; k < 8; ++k) {
            float4 q = p4[k];
            v[4 * k + 0] = q.x; v[4 * k + 1] = q.y;
            v[4 * k + 2] = q.z; v[4 * k + 3] = q.w;
        }

        #pragma unroll
        for (int j = 0; j < 32; ++j) {
            int c = __shfl_sync(0xffffffffu, lab, j);
            ac[c * 32] += v[j];               // acc[w][c*32 + lane]
        }

        // counts: one RMW per distinct label per 32 pixels
        unsigned m = __match_any_sync(0xffffffffu, lab);
        if ((__ffs(m) - 1) == lane)
            cnt[w][lab] += (float)__popc(m);
    }

    __syncthreads();
    for (int i = threadIdx.x; i < C_ * D_; i += 256) {
        float s = 0.f;
        #pragma unroll
        for (int w2 = 0; w2 < K1_WARPS; ++w2) s += acc[w2][i];
        atomicAdd(&g_sum[i], s);
    }
    if (threadIdx.x < C_) {
        float s = 0.f;
        #pragma unroll
        for (int w2 = 0; w2 < K1_WARPS; ++w2) s += cnt[w2][threadIdx.x];
        atomicAdd(&g_cnt[threadIdx.x], s);
    }
}

// ---------------- K2: centers + norms (1 block, 608 thr = 19 warps) --------
__global__ void k_centers() {
    int i = threadIdx.x;
    if (i >= C_ * D_) return;
    int c = i >> 5, d = i & 31;               // warp == class
    float count = g_cnt[c];
    float ctr = g_sum[i] / fmaxf(count, 1.f);
    g_center[i] = ctr;
    float s = ctr * ctr;
    #pragma unroll
    for (int o = 16; o; o >>= 1) s += __shfl_xor_sync(0xffffffffu, s, o);
    if (d == 0) g_cnorm[c] = sqrtf(s);
}

// ---------------- K3: per-pixel cosine vs class center ----------------------
#define K3_BLOCKS 2048
__global__ void __launch_bounds__(256) k_cos(const float* __restrict__ in,
                                             const void* __restrict__ tgt) {
    __shared__ float cs[C_ * 33];   // pitch 33 -> conflict-free center reads
    __shared__ float cn[C_];
    __shared__ float sbin[C_];

    const int t = threadIdx.x;
    for (int i = t; i < C_ * D_; i += 256) {
        int c = i >> 5, d = i & 31;
        cs[c * 33 + d] = g_center[i];
    }
    if (t < C_) { cn[t] = g_cnorm[t]; sbin[t] = 0.f; }
    __syncthreads();

    const int is64 = g_is64;
    const long long* t64 = (const long long*)tgt;
    const int*       t32 = (const int*)tgt;

    const int stride = K3_BLOCKS * 256;
    for (int p = blockIdx.x * 256 + t; p < N_; p += stride) {
        const int b  = p >> 18;
        const int hw = p & (HW_ - 1);
        const float* bp = in + (size_t)b * ((size_t)D_ * HW_) + hw;
        int c = is64 ? (int)t64[p] : t32[p];
        const float* crow = &cs[c * 33];

        float dot = 0.f, ss = 0.f;
        #pragma unroll
        for (int d = 0; d < D_; ++d) {
            float v = bp[(size_t)d * HW_];
            dot += v * crow[d];
            ss  += v * v;
        }
        float fn  = sqrtf(ss);
        float den = fmaxf(fn * cn[c], EPS_);
        atomicAdd(&sbin[c], dot / den);
    }

    __syncthreads();
    if (t < C_) atomicAdd(&g_segcos[t], sbin[t]);
}

// ---------------- K4: finalize (sim_loss + diff_loss) -----------------------
__global__ void k_final(float* __restrict__ out) {
    __shared__ float cs[C_ * 33];
    __shared__ float cn[C_];
    const int t = threadIdx.x;  // 32 threads
    for (int i = t; i < C_ * D_; i += 32) {
        int c = i >> 5, d = i & 31;
        cs[c * 33 + d] = g_center[i];
    }
    if (t < C_) cn[t] = g_cnorm[t];
    __syncwarp();

    float total = 0.f;
    if (t < C_) {
        float count   = g_cnt[t];
        bool  present = count > 0.f;
        float denom   = fmaxf(count, 1.f);
        float sim     = present ? (1.f - g_segcos[t] / denom) : 0.f;

        float ci[D_];
        #pragma unroll
        for (int d = 0; d < D_; ++d) ci[d] = cs[t * 33 + d];

        float accd = 0.f;
        for (int j = 0; j < C_; ++j) {
            float dot = 0.f;
            #pragma unroll
            for (int d = 0; d < D_; ++d) dot += ci[d] * cs[j * 33 + d];
            float cosv = dot / fmaxf(cn[t] * cn[j], EPS_);
            accd += (j == t) ? (1.f - cosv) : fmaxf(cosv, 0.f);
        }
        float diff = accd / (float)C_;
        total = sim + (present ? diff : 0.f);
    }
    #pragma unroll
    for (int o = 16; o; o >>= 1) total += __shfl_xor_sync(0xffffffffu, total, o);
    if (t == 0) out[0] = total;
}

// ---------------- launcher --------------------------------------------------
extern "C" void kernel_launch(void* const* d_in, const int* in_sizes, int n_in,
                              void* d_out, int out_size) {
    (void)in_sizes; (void)n_in; (void)out_size;
    const float* in  = (const float*)d_in[0];
    const void*  tgt = d_in[1];
    float*       out = (float*)d_out;

    k_zero<<<1, 640>>>(tgt);
    k_sums<<<K1_BLOCKS, 256>>>(in, tgt);
    k_centers<<<1, 608>>>();
    k_cos<<<K3_BLOCKS, 256>>>(in, tgt);
    k_final<<<1, 32>>>(out);
}

// round 4
// speedup vs baseline: 1.4881x; 1.4881x over previous
#include <cuda_runtime.h>

// Problem constants (fixed for this instance)
#define HW_   262144          // H*W = 512*512
#define D_    32
#define B_    8
#define C_    19
#define N_    2097152         // B*H*W
#define NGRP_ 65536           // N / 32
#define EPS_  1e-8f

// ---------------- scratch (device globals; no allocation allowed) ----------
__device__ float g_sumv[C_ * D_];    // per-class sums of x
__device__ float g_sumn[C_ * D_];    // per-class sums of x/||x||
__device__ float g_cnt[C_];          // per-class counts
__device__ int   g_is64;             // targets dtype flag

// ---------------- K0: zero scratch + detect target dtype -------------------
__global__ void k_zero(const void* __restrict__ tgt) {
    int i = threadIdx.x;
    if (i < C_ * D_) { g_sumv[i] = 0.f; g_sumn[i] = 0.f; }
    if (i < C_) g_cnt[i] = 0.f;
    if (i == 639) {
        // int64 labels in [0,19): every odd 32-bit word is 0.
        const unsigned* w = (const unsigned*)tgt;
        int is64 = 1;
        #pragma unroll
        for (int k = 0; k < 16; k++)
            if (w[2 * k + 1] != 0u) is64 = 0;
        g_is64 = is64;
    }
}

// ---------------- K1: fused segment sums (x and x/||x||) + counts -----------
// lane = pixel for loads (coalesced, 1 line per LDG), transpose via padded
// smem tile, then lane = dim for the non-atomic per-warp RMW chain.
#define K1_BLOCKS 888
#define K1_WARPS  4

__global__ void __launch_bounds__(128) k_fused(const float* __restrict__ in,
                                               const void* __restrict__ tgt) {
    __shared__ float2 acc[K1_WARPS][C_ * D_];     // (.x = sum, .y = nsum)
    __shared__ float  tile[K1_WARPS][D_ * 33];    // pitch-33: conflict-free
    __shared__ float  cnt[K1_WARPS][C_];

    const int w    = threadIdx.x >> 5;
    const int lane = threadIdx.x & 31;
    const int is64 = g_is64;

    for (int i = lane; i < C_ * D_; i += 32) acc[w][i] = make_float2(0.f, 0.f);
    if (lane < C_) cnt[w][lane] = 0.f;
    __syncwarp();

    const long long* t64 = (const long long*)tgt;
    const int*       t32 = (const int*)tgt;

    const int gw      = blockIdx.x * K1_WARPS + w;
    const int nwarps  = K1_BLOCKS * K1_WARPS;
    float*  tw = tile[w];
    float2* aw = acc[w];

    for (int g = gw; g < NGRP_; g += nwarps) {
        const int p0 = g * 32;
        const int p  = p0 + lane;                 // this lane's pixel
        const int b  = p0 >> 18;
        const int hw = (p0 & (HW_ - 1)) + lane;
        const float* bp = in + (size_t)b * ((size_t)D_ * HW_) + hw;

        int lab = is64 ? (int)t64[p] : t32[p];

        // coalesced: per instruction, 32 lanes cover one 128B line
        float v[D_];
        float ss = 0.f;
        #pragma unroll
        for (int d = 0; d < D_; ++d) {
            v[d] = bp[(size_t)d * HW_];
            ss += v[d] * v[d];
        }
        float r = rsqrtf(fmaxf(ss, 1e-24f));      // 1/||x||

        // transpose through tile: tile[d][pixel], conflict-free both ways
        #pragma unroll
        for (int d = 0; d < D_; ++d) tw[d * 33 + lane] = v[d];
        __syncwarp();

        // RMW chain with lane = dim; each (class, dim) cell owned by this
        // lane of this warp -> race-free without atomics.
        #pragma unroll
        for (int j = 0; j < 32; ++j) {
            int   c   = __shfl_sync(0xffffffffu, lab, j);
            float rj  = __shfl_sync(0xffffffffu, r, j);
            float val = tw[lane * 33 + j];
            float2 a  = aw[c * 32 + lane];
            a.x += val;
            a.y += val * rj;
            aw[c * 32 + lane] = a;
        }

        // counts: one RMW per distinct label per group
        unsigned m = __match_any_sync(0xffffffffu, lab);
        if ((__ffs(m) - 1) == lane)
            cnt[w][lab] += (float)__popc(m);
        __syncwarp();                             // tile reuse barrier
    }

    __syncthreads();
    for (int i = threadIdx.x; i < C_ * D_; i += 128) {
        float sx = 0.f, sy = 0.f;
        #pragma unroll
        for (int w2 = 0; w2 < K1_WARPS; ++w2) {
            float2 a = acc[w2][i];
            sx += a.x; sy += a.y;
        }
        atomicAdd(&g_sumv[i], sx);
        atomicAdd(&g_sumn[i], sy);
    }
    if (threadIdx.x < C_) {
        float s = 0.f;
        #pragma unroll
        for (int w2 = 0; w2 < K1_WARPS; ++w2) s += cnt[w2][threadIdx.x];
        atomicAdd(&g_cnt[threadIdx.x], s);
    }
}

// ---------------- K2: finalize (centers, seg_cos, sim + diff) ---------------
// 1 block, 608 threads = 19 warps, warp == class.
__global__ void k_final(float* __restrict__ out) {
    __shared__ float cs[C_ * 33];    // centers, pitch 33
    __shared__ float cn[C_];         // center norms
    __shared__ float per_class[C_];

    const int t    = threadIdx.x;
    const int c    = t >> 5;
    const int d    = t & 31;
    const int i    = c * 32 + d;

    float count = g_cnt[c];
    float denom = fmaxf(count, 1.f);
    float ctr   = g_sumv[i] / denom;
    cs[c * 33 + d] = ctr;

    float s = ctr * ctr;
    #pragma unroll
    for (int o = 16; o; o >>= 1) s += __shfl_xor_sync(0xffffffffu, s, o);
    float cnorm = sqrtf(s);
    if (d == 0) cn[c] = cnorm;

    // seg_cos_c = dot(sum_p x_p/||x_p||, center_c) / ||center_c||
    float sc = g_sumn[i] * ctr;
    #pragma unroll
    for (int o = 16; o; o >>= 1) sc += __shfl_xor_sync(0xffffffffu, sc, o);
    float segcos = sc / fmaxf(cnorm, 1e-30f);

    __syncthreads();

    // diff row c of the 19x19 center-cosine matrix
    float ci = cs[c * 33 + d];
    float accd = 0.f;
    for (int j = 0; j < C_; ++j) {
        float dot = ci * cs[j * 33 + d];
        #pragma unroll
        for (int o = 16; o; o >>= 1) dot += __shfl_xor_sync(0xffffffffu, dot, o);
        float cosv = dot / fmaxf(cnorm * cn[j], EPS_);
        accd += (j == c) ? (1.f - cosv) : fmaxf(cosv, 0.f);
    }

    if (d == 0) {
        bool present = count > 0.f;
        float sim  = present ? (1.f - segcos / denom) : 0.f;
        float diff = present ? (accd / (float)C_) : 0.f;
        per_class[c] = sim + diff;
    }
    __syncthreads();

    if (t < 32) {
        float tot = (t < C_) ? per_class[t] : 0.f;
        #pragma unroll
        for (int o = 16; o; o >>= 1) tot += __shfl_xor_sync(0xffffffffu, tot, o);
        if (t == 0) out[0] = tot;
    }
}

// ---------------- launcher --------------------------------------------------
extern "C" void kernel_launch(void* const* d_in, const int* in_sizes, int n_in,
                              void* d_out, int out_size) {
    (void)in_sizes; (void)n_in; (void)out_size;
    const float* in  = (const float*)d_in[0];
    const void*  tgt = d_in[1];
    float*       out = (float*)d_out;

    k_zero<<<1, 640>>>(tgt);
    k_fused<<<K1_BLOCKS, 128>>>(in, tgt);
    k_final<<<1, 608>>>(out);
}